// round 1
// baseline (speedup 1.0000x reference)
#include <cuda_runtime.h>
#include <mma.h>

using namespace nvcuda;

#define BATCH 4
#define CH    512
#define CQK   64
#define NPIX  4096
#define QKV_ROWS 640
#define EPS   1e-5f

// ---------------- scratch (device globals; allocation-free) ----------------
__device__ float g_qkv[(size_t)BATCH * QKV_ROWS * NPIX];      // q(64) | k(64) | v(512) rows per batch
__device__ float g_energy[(size_t)BATCH * NPIX * NPIX];       // energy -> attn in place
__device__ float g_ao[(size_t)BATCH * CH * NPIX];             // attention output
__device__ float g_mean[CH];
__device__ float g_var[CH];

// ---------------- generic tf32 WMMA GEMM ----------------
// D[b][m][n] = sum_k A[b](m,k) * B[b](k,n) (+ bias[m])
// A element (m,k) at A + b*Abatch + m*Asm + k*Ask   (one of Asm/Ask == 1)
// B element (k,n) at B + b*Bbatch + k*Bsk + n*Bsn   (one of Bsk/Bsn == 1)
// D row-major with leading dim Dsm.
// Requires: K % 16 == 0, N % 128 == 0. M guarded.

#define BM 128
#define BN 128
#define BKT 16
#define LDAS (BM + 4)
#define LDBS (BN + 4)

__global__ __launch_bounds__(256) void gemm_tf32(
    const float* __restrict__ A, size_t Abatch, int Asm, int Ask,
    const float* __restrict__ B, size_t Bbatch, int Bsk, int Bsn,
    float* __restrict__ D, size_t Dbatch, int Dsm,
    const float* __restrict__ bias, int M, int N, int K)
{
    __shared__ float As[BKT][LDAS];
    __shared__ float Bs[BKT][LDBS];
    __shared__ float stage[8][256];

    const int b = blockIdx.z;
    const float* Ab = A + (size_t)b * Abatch;
    const float* Bb = B + (size_t)b * Bbatch;
    float* Db = D + (size_t)b * Dbatch;

    const int m0 = blockIdx.y * BM;
    const int n0 = blockIdx.x * BN;
    const int tid = threadIdx.x;
    const int warp = tid >> 5;
    const int lane = tid & 31;
    const int wm = (warp >> 1) * 32;   // warp tile: 32 (m) x 64 (n)
    const int wn = (warp & 1) * 64;

    wmma::fragment<wmma::accumulator, 16, 16, 8, float> acc[2][4];
#pragma unroll
    for (int i = 0; i < 2; i++)
#pragma unroll
        for (int j = 0; j < 4; j++)
            wmma::fill_fragment(acc[i][j], 0.0f);

    for (int k0 = 0; k0 < K; k0 += BKT) {
        // ---- load A tile into As[k][m] ----
        if (Asm == 1) {  // m contiguous in gmem
            for (int idx = tid; idx < BM * BKT; idx += 256) {
                int k = idx / BM, m = idx - k * BM;
                int gm = m0 + m;
                As[k][m] = (gm < M) ? Ab[(size_t)gm + (size_t)(k0 + k) * Ask] : 0.0f;
            }
        } else {         // k contiguous in gmem
            for (int idx = tid; idx < BM * BKT; idx += 256) {
                int m = idx / BKT, k = idx - m * BKT;
                int gm = m0 + m;
                As[k][m] = (gm < M) ? Ab[(size_t)gm * Asm + (size_t)(k0 + k)] : 0.0f;
            }
        }
        // ---- load B tile into Bs[k][n] ----
        if (Bsn == 1) {  // n contiguous
            for (int idx = tid; idx < BKT * BN; idx += 256) {
                int k = idx / BN, n = idx - k * BN;
                Bs[k][n] = Bb[(size_t)(k0 + k) * Bsk + (size_t)(n0 + n)];
            }
        } else {         // k contiguous
            for (int idx = tid; idx < BKT * BN; idx += 256) {
                int n = idx / BKT, k = idx - n * BKT;
                Bs[k][n] = Bb[(size_t)(n0 + n) * Bsn + (size_t)(k0 + k)];
            }
        }
        __syncthreads();

#pragma unroll
        for (int ks = 0; ks < BKT; ks += 8) {
            wmma::fragment<wmma::matrix_a, 16, 16, 8, wmma::precision::tf32, wmma::col_major> af[2];
            wmma::fragment<wmma::matrix_b, 16, 16, 8, wmma::precision::tf32, wmma::row_major> bf[4];
#pragma unroll
            for (int i = 0; i < 2; i++) {
                wmma::load_matrix_sync(af[i], &As[ks][wm + i * 16], LDAS);
#pragma unroll
                for (int t = 0; t < af[i].num_elements; t++)
                    af[i].x[t] = wmma::__float_to_tf32(af[i].x[t]);
            }
#pragma unroll
            for (int j = 0; j < 4; j++) {
                wmma::load_matrix_sync(bf[j], &Bs[ks][wn + j * 16], LDBS);
#pragma unroll
                for (int t = 0; t < bf[j].num_elements; t++)
                    bf[j].x[t] = wmma::__float_to_tf32(bf[j].x[t]);
            }
#pragma unroll
            for (int i = 0; i < 2; i++)
#pragma unroll
                for (int j = 0; j < 4; j++)
                    wmma::mma_sync(acc[i][j], af[i], bf[j], acc[i][j]);
        }
        __syncthreads();
    }

    // ---- epilogue: stage each 16x16 frag through smem, add bias, store ----
#pragma unroll
    for (int i = 0; i < 2; i++)
#pragma unroll
        for (int j = 0; j < 4; j++) {
            wmma::store_matrix_sync(&stage[warp][0], acc[i][j], 16, wmma::mem_row_major);
            __syncwarp();
            for (int e = lane; e < 256; e += 32) {
                int r = e >> 4, c = e & 15;
                int gm = m0 + wm + i * 16 + r;
                int gn = n0 + wn + j * 16 + c;
                if (gm < M) {
                    float val = stage[warp][e];
                    if (bias) val += bias[gm];
                    Db[(size_t)gm * Dsm + gn] = val;
                }
            }
            __syncwarp();
        }
}

// ---------------- row softmax (in place), one block per row ----------------
__global__ __launch_bounds__(256) void softmax_rows(float* __restrict__ E)
{
    __shared__ float row[NPIX];
    __shared__ float red[256];
    float* r = E + (size_t)blockIdx.x * NPIX;
    const int tid = threadIdx.x;

    float mx = -3.402823466e+38f;
    for (int j = tid; j < NPIX; j += 256) {
        float v = r[j];
        row[j] = v;
        mx = fmaxf(mx, v);
    }
    red[tid] = mx;
    __syncthreads();
    for (int s = 128; s > 0; s >>= 1) {
        if (tid < s) red[tid] = fmaxf(red[tid], red[tid + s]);
        __syncthreads();
    }
    const float m = red[0];
    __syncthreads();

    float sum = 0.0f;
    for (int j = tid; j < NPIX; j += 256) {
        float e = expf(row[j] - m);
        row[j] = e;
        sum += e;
    }
    red[tid] = sum;
    __syncthreads();
    for (int s = 128; s > 0; s >>= 1) {
        if (tid < s) red[tid] += red[tid + s];
        __syncthreads();
    }
    const float inv = 1.0f / red[0];
    __syncthreads();

    for (int j = tid; j < NPIX; j += 256)
        r[j] = row[j] * inv;
}

// ---------------- residual + per-channel batch stats ----------------
__global__ __launch_bounds__(256) void residual_stats(
    const float* __restrict__ ao, const float* __restrict__ x,
    const float* __restrict__ gamma, float* __restrict__ out,
    float* __restrict__ mean, float* __restrict__ var)
{
    __shared__ float r1[256], r2[256];
    const int c = blockIdx.x;
    const float g = gamma[0];
    float s1 = 0.0f, s2 = 0.0f;
#pragma unroll
    for (int b = 0; b < BATCH; b++) {
        size_t base = ((size_t)b * CH + c) * NPIX;
        for (int n = threadIdx.x; n < NPIX; n += 256) {
            float v = g * ao[base + n] + x[base + n];
            out[base + n] = v;
            s1 += v;
            s2 += v * v;
        }
    }
    r1[threadIdx.x] = s1;
    r2[threadIdx.x] = s2;
    __syncthreads();
    for (int s = 128; s > 0; s >>= 1) {
        if (threadIdx.x < s) {
            r1[threadIdx.x] += r1[threadIdx.x + s];
            r2[threadIdx.x] += r2[threadIdx.x + s];
        }
        __syncthreads();
    }
    if (threadIdx.x == 0) {
        const float cnt = (float)(BATCH * NPIX);
        float m = r1[0] / cnt;
        mean[c] = m;
        var[c] = r2[0] / cnt - m * m;
    }
}

// ---------------- BN normalize (in place on d_out) ----------------
__global__ __launch_bounds__(256) void bn_apply(
    float* __restrict__ out, const float* __restrict__ mean,
    const float* __restrict__ var, const float* __restrict__ w,
    const float* __restrict__ bb)
{
    size_t i = (size_t)blockIdx.x * 256 + threadIdx.x;
    const size_t total = (size_t)BATCH * CH * NPIX;
    if (i < total) {
        int c = (int)((i / NPIX) % CH);
        out[i] = (out[i] - mean[c]) * rsqrtf(var[c] + EPS) * w[c] + bb[c];
    }
}

// ---------------- launch ----------------
extern "C" void kernel_launch(void* const* d_in, const int* in_sizes, int n_in,
                              void* d_out, int out_size)
{
    const float* x     = (const float*)d_in[0];
    const float* Wq    = (const float*)d_in[1];
    const float* bq    = (const float*)d_in[2];
    const float* Wk    = (const float*)d_in[3];
    const float* bk    = (const float*)d_in[4];
    const float* Wv    = (const float*)d_in[5];
    const float* bv    = (const float*)d_in[6];
    const float* gamma = (const float*)d_in[7];
    const float* bn_w  = (const float*)d_in[8];
    const float* bn_b  = (const float*)d_in[9];
    float* out = (float*)d_out;

    float *qkv, *energy, *ao, *mean, *var;
    cudaGetSymbolAddress((void**)&qkv,    g_qkv);
    cudaGetSymbolAddress((void**)&energy, g_energy);
    cudaGetSymbolAddress((void**)&ao,     g_ao);
    cudaGetSymbolAddress((void**)&mean,   g_mean);
    cudaGetSymbolAddress((void**)&var,    g_var);

    const size_t xbs   = (size_t)CH * NPIX;         // x batch stride
    const size_t qkvbs = (size_t)QKV_ROWS * NPIX;   // qkv batch stride
    dim3 blk(256);

    // q = Wq @ x  (M=64, K=512)
    gemm_tf32<<<dim3(NPIX / BN, 1, BATCH), blk>>>(
        Wq, 0, CH, 1, x, xbs, NPIX, 1,
        qkv, qkvbs, NPIX, bq, CQK, NPIX, CH);
    // k = Wk @ x
    gemm_tf32<<<dim3(NPIX / BN, 1, BATCH), blk>>>(
        Wk, 0, CH, 1, x, xbs, NPIX, 1,
        qkv + (size_t)CQK * NPIX, qkvbs, NPIX, bk, CQK, NPIX, CH);
    // v = Wv @ x  (M=512)
    gemm_tf32<<<dim3(NPIX / BN, CH / BM, BATCH), blk>>>(
        Wv, 0, CH, 1, x, xbs, NPIX, 1,
        qkv + (size_t)2 * CQK * NPIX, qkvbs, NPIX, bv, CH, NPIX, CH);

    // energy[i][j] = sum_k q[k][i] * k[k][j]   (M=N=4096, K=64)
    gemm_tf32<<<dim3(NPIX / BN, NPIX / BM, BATCH), blk>>>(
        qkv, qkvbs, 1, NPIX,
        qkv + (size_t)CQK * NPIX, qkvbs, NPIX, 1,
        energy, (size_t)NPIX * NPIX, NPIX, nullptr, NPIX, NPIX, CQK);

    // softmax over rows
    softmax_rows<<<BATCH * NPIX, 256>>>(energy);

    // ao[c][i] = sum_j v[c][j] * attn[i][j]   (M=512, K=4096)
    gemm_tf32<<<dim3(NPIX / BN, CH / BM, BATCH), blk>>>(
        qkv + (size_t)2 * CQK * NPIX, qkvbs, NPIX, 1,
        energy, (size_t)NPIX * NPIX, 1, NPIX,
        ao, (size_t)CH * NPIX, NPIX, nullptr, CH, NPIX, NPIX);

    // residual + stats, then BN
    residual_stats<<<CH, 256>>>(ao, x, gamma, out, mean, var);
    bn_apply<<<((size_t)BATCH * CH * NPIX) / 256, 256>>>(out, mean, var, bn_w, bn_b);
}

// round 2
// speedup vs baseline: 1.5346x; 1.5346x over previous
#include <cuda_runtime.h>
#include <mma.h>

using namespace nvcuda;

#define BATCH 4
#define CH    512
#define CQK   64
#define NPIX  4096
#define QKV_ROWS 640
#define EPS   1e-5f

// ---------------- scratch (device globals; allocation-free) ----------------
__device__ float g_qkv[(size_t)BATCH * QKV_ROWS * NPIX];   // q(64)|k(64)|v(512) rows per batch
__device__ float g_energy[(size_t)BATCH * NPIX * NPIX];    // energy -> attn in place
__device__ float g_ao[(size_t)BATCH * CH * NPIX];          // attention output
__device__ float g_mean[CH];
__device__ float g_var[CH];

// ---------------- cp.async helpers ----------------
__device__ __forceinline__ void cp16(float* dst, const float* src, int sz) {
    unsigned d = (unsigned)__cvta_generic_to_shared(dst);
    asm volatile("cp.async.cg.shared.global [%0], [%1], 16, %2;\n"
                 :: "r"(d), "l"(src), "r"(sz));
}
__device__ __forceinline__ void cp_commit() {
    asm volatile("cp.async.commit_group;\n" ::: "memory");
}
__device__ __forceinline__ void cp_wait_all() {
    asm volatile("cp.async.wait_group 0;\n" ::: "memory");
}

// ---------------- pipelined tf32 WMMA GEMM ----------------
// D[b](m,n) = sum_k A[b](m,k) * B[b](k,n) (+ bias[m])
// AMODE 0: A(m,k) = A[m*lda + k]   (k contiguous)   -> As[m][k],  row_major frag
// AMODE 1: A(m,k) = A[k*lda + m]   (m contiguous)   -> As[k][m],  col_major frag
// BMODE 0: B(k,n) = B[k*ldb + n]   (n contiguous)   -> Bs[k][n],  row_major frag
// BMODE 1: B(k,n) = B[n*ldb + k]   (k contiguous)   -> Bs[n][k],  col_major frag
// Tile 128x128, BK=16, 256 threads, 2-stage cp.async pipeline.
// Requires: N == 4096 tiles fully covered by grid.x, K % 16 == 0, lda/ldb % 4 == 0.

#define BM 128
#define BN 128
#define BK 16
#define LDA0 20    // As[128][20]  (AMODE 0)
#define LDA1 132   // As[16][132]  (AMODE 1)
#define LDB0 132   // Bs[16][132]  (BMODE 0)
#define LDB1 20    // Bs[128][20]  (BMODE 1)

template<int AMODE, int BMODE, bool HAS_BIAS>
__global__ __launch_bounds__(256, 2) void gemm_tf32_pipe(
    const float* __restrict__ A, size_t Abatch, int lda,
    const float* __restrict__ B, size_t Bbatch, int ldb,
    float* __restrict__ D, size_t Dbatch, int ldd,
    const float* __restrict__ bias, int M, int K)
{
    constexpr int ASZ = (AMODE == 0) ? BM * LDA0 : BK * LDA1;
    constexpr int BSZ = (BMODE == 0) ? BK * LDB0 : BN * LDB1;
    __shared__ float sm[2][ASZ + BSZ];

    const int b = blockIdx.z;
    const float* Ab = A + (size_t)b * Abatch;
    const float* Bb = B + (size_t)b * Bbatch;
    float* Db = D + (size_t)b * Dbatch;

    const int m0 = blockIdx.y * BM;
    const int n0 = blockIdx.x * BN;
    const int tid = threadIdx.x;
    const int warp = tid >> 5;
    const int lane = tid & 31;
    const int wm = (warp >> 1) * 32;   // warp tile 32(m) x 64(n)
    const int wn = (warp & 1) * 64;

    wmma::fragment<wmma::accumulator, 16, 16, 8, float> acc[2][4];
#pragma unroll
    for (int i = 0; i < 2; i++)
#pragma unroll
        for (int j = 0; j < 4; j++)
            wmma::fill_fragment(acc[i][j], 0.0f);

    // ---- tile loader (cp.async, all 16B) ----
    auto load_tile = [&](int s, int k0) {
        float* As = sm[s];
        float* Bs = sm[s] + ASZ;
        // A: 512 chunks of 16B
#pragma unroll
        for (int r = 0; r < 2; r++) {
            int c = tid + r * 256;
            if (AMODE == 0) {
                int m = c >> 2, kc = c & 3;
                int gm = m0 + m;
                int ok = (gm < M) ? 16 : 0;
                int gmc = (gm < M) ? gm : (M - 1);
                cp16(&As[m * LDA0 + kc * 4], Ab + (size_t)gmc * lda + k0 + kc * 4, ok);
            } else {
                int k = c >> 5, mc = c & 31;
                cp16(&As[k * LDA1 + mc * 4], Ab + (size_t)(k0 + k) * lda + m0 + mc * 4, 16);
            }
        }
        // B: 512 chunks of 16B
#pragma unroll
        for (int r = 0; r < 2; r++) {
            int c = tid + r * 256;
            if (BMODE == 0) {
                int k = c >> 5, nc = c & 31;
                cp16(&Bs[k * LDB0 + nc * 4], Bb + (size_t)(k0 + k) * ldb + n0 + nc * 4, 16);
            } else {
                int n = c >> 2, kc = c & 3;
                cp16(&Bs[n * LDB1 + kc * 4], Bb + (size_t)(n0 + n) * ldb + k0 + kc * 4, 16);
            }
        }
    };

    auto compute_tile = [&](int s) {
        const float* As = sm[s];
        const float* Bs = sm[s] + ASZ;
#pragma unroll
        for (int ks = 0; ks < BK; ks += 8) {
            wmma::fragment<wmma::matrix_a, 16, 16, 8, wmma::precision::tf32, wmma::row_major> ar[2];
            wmma::fragment<wmma::matrix_a, 16, 16, 8, wmma::precision::tf32, wmma::col_major> ac[2];
#pragma unroll
            for (int i = 0; i < 2; i++) {
                if (AMODE == 0) {
                    wmma::load_matrix_sync(ar[i], &As[(wm + i * 16) * LDA0 + ks], LDA0);
#pragma unroll
                    for (int t = 0; t < 4; t++) ar[i].x[t] = wmma::__float_to_tf32(ar[i].x[t]);
                } else {
                    wmma::load_matrix_sync(ac[i], &As[ks * LDA1 + wm + i * 16], LDA1);
#pragma unroll
                    for (int t = 0; t < 4; t++) ac[i].x[t] = wmma::__float_to_tf32(ac[i].x[t]);
                }
            }
#pragma unroll
            for (int j = 0; j < 4; j++) {
                wmma::fragment<wmma::matrix_b, 16, 16, 8, wmma::precision::tf32, wmma::row_major> br;
                wmma::fragment<wmma::matrix_b, 16, 16, 8, wmma::precision::tf32, wmma::col_major> bc;
                if (BMODE == 0) {
                    wmma::load_matrix_sync(br, &Bs[ks * LDB0 + wn + j * 16], LDB0);
#pragma unroll
                    for (int t = 0; t < 4; t++) br.x[t] = wmma::__float_to_tf32(br.x[t]);
                } else {
                    wmma::load_matrix_sync(bc, &Bs[(wn + j * 16) * LDB1 + ks], LDB1);
#pragma unroll
                    for (int t = 0; t < 4; t++) bc.x[t] = wmma::__float_to_tf32(bc.x[t]);
                }
#pragma unroll
                for (int i = 0; i < 2; i++) {
                    if (AMODE == 0 && BMODE == 0) wmma::mma_sync(acc[i][j], ar[i], br, acc[i][j]);
                    if (AMODE == 0 && BMODE == 1) wmma::mma_sync(acc[i][j], ar[i], bc, acc[i][j]);
                    if (AMODE == 1 && BMODE == 0) wmma::mma_sync(acc[i][j], ac[i], br, acc[i][j]);
                    if (AMODE == 1 && BMODE == 1) wmma::mma_sync(acc[i][j], ac[i], bc, acc[i][j]);
                }
            }
        }
    };

    const int KT = K / BK;
    load_tile(0, 0);
    cp_commit();
    for (int kt = 0; kt < KT; kt++) {
        cp_wait_all();
        __syncthreads();
        if (kt + 1 < KT) {
            load_tile((kt + 1) & 1, (kt + 1) * BK);
            cp_commit();
        }
        compute_tile(kt & 1);
    }

    // ---- epilogue ----
    if (!HAS_BIAS) {
#pragma unroll
        for (int i = 0; i < 2; i++) {
            int gm = m0 + wm + i * 16;
            if (gm < M) {
#pragma unroll
                for (int j = 0; j < 4; j++)
                    wmma::store_matrix_sync(Db + (size_t)gm * ldd + n0 + wn + j * 16,
                                            acc[i][j], ldd, wmma::mem_row_major);
            }
        }
    } else {
        __syncthreads();  // smem reuse for staging
        float* stg = &sm[0][warp * 256];
#pragma unroll
        for (int i = 0; i < 2; i++)
#pragma unroll
            for (int j = 0; j < 4; j++) {
                wmma::store_matrix_sync(stg, acc[i][j], 16, wmma::mem_row_major);
                __syncwarp();
#pragma unroll
                for (int e = 0; e < 8; e++) {
                    int el = lane + e * 32;
                    int r = el >> 4, cc = el & 15;
                    int gm = m0 + wm + i * 16 + r;
                    int gn = n0 + wn + j * 16 + cc;
                    if (gm < M)
                        Db[(size_t)gm * ldd + gn] = stg[el] + bias[gm];
                }
                __syncwarp();
            }
    }
}

// ---------------- row softmax (in place), one block per row ----------------
__global__ __launch_bounds__(256) void softmax_rows(float* __restrict__ E)
{
    __shared__ float row[NPIX];
    __shared__ float red[256];
    float* r = E + (size_t)blockIdx.x * NPIX;
    const int tid = threadIdx.x;

    float mx = -3.402823466e+38f;
    for (int j = tid; j < NPIX; j += 256) {
        float v = r[j];
        row[j] = v;
        mx = fmaxf(mx, v);
    }
    red[tid] = mx;
    __syncthreads();
    for (int s = 128; s > 0; s >>= 1) {
        if (tid < s) red[tid] = fmaxf(red[tid], red[tid + s]);
        __syncthreads();
    }
    const float m = red[0];
    __syncthreads();

    float sum = 0.0f;
    for (int j = tid; j < NPIX; j += 256) {
        float e = __expf(row[j] - m);
        row[j] = e;
        sum += e;
    }
    red[tid] = sum;
    __syncthreads();
    for (int s = 128; s > 0; s >>= 1) {
        if (tid < s) red[tid] += red[tid + s];
        __syncthreads();
    }
    const float inv = 1.0f / red[0];
    __syncthreads();

    for (int j = tid; j < NPIX; j += 256)
        r[j] = row[j] * inv;
}

// ---------------- per-channel batch stats (no output write) ----------------
__global__ __launch_bounds__(256) void residual_stats(
    const float* __restrict__ ao, const float* __restrict__ x,
    const float* __restrict__ gamma,
    float* __restrict__ mean, float* __restrict__ var)
{
    __shared__ float r1[256], r2[256];
    const int c = blockIdx.x;
    const float g = gamma[0];
    float s1 = 0.0f, s2 = 0.0f;
#pragma unroll
    for (int b = 0; b < BATCH; b++) {
        const float4* a4 = (const float4*)(ao + ((size_t)b * CH + c) * NPIX);
        const float4* x4 = (const float4*)(x  + ((size_t)b * CH + c) * NPIX);
        for (int n = threadIdx.x; n < NPIX / 4; n += 256) {
            float4 av = a4[n], xv = x4[n];
            float v0 = g * av.x + xv.x, v1 = g * av.y + xv.y;
            float v2 = g * av.z + xv.z, v3 = g * av.w + xv.w;
            s1 += v0 + v1 + v2 + v3;
            s2 += v0 * v0 + v1 * v1 + v2 * v2 + v3 * v3;
        }
    }
    r1[threadIdx.x] = s1;
    r2[threadIdx.x] = s2;
    __syncthreads();
    for (int s = 128; s > 0; s >>= 1) {
        if (threadIdx.x < s) {
            r1[threadIdx.x] += r1[threadIdx.x + s];
            r2[threadIdx.x] += r2[threadIdx.x + s];
        }
        __syncthreads();
    }
    if (threadIdx.x == 0) {
        const float cnt = (float)(BATCH * NPIX);
        float m = r1[0] / cnt;
        mean[c] = m;
        var[c] = r2[0] / cnt - m * m;
    }
}

// ---------------- BN apply: out = ((g*ao + x) - mean) * rstd * w + b ----------------
__global__ __launch_bounds__(256) void bn_apply(
    const float* __restrict__ ao, const float* __restrict__ x,
    const float* __restrict__ gamma,
    float* __restrict__ out, const float* __restrict__ mean,
    const float* __restrict__ var, const float* __restrict__ w,
    const float* __restrict__ bb)
{
    size_t i4 = (size_t)blockIdx.x * 256 + threadIdx.x;
    const float g = gamma[0];
    int c = (int)((i4 >> 10) & (CH - 1));           // 1024 float4 per (b,c) row
    float sc = rsqrtf(var[c] + EPS) * w[c];
    float sh = bb[c] - mean[c] * sc;
    float4 av = ((const float4*)ao)[i4];
    float4 xv = ((const float4*)x)[i4];
    float4 o;
    o.x = (g * av.x + xv.x) * sc + sh;
    o.y = (g * av.y + xv.y) * sc + sh;
    o.z = (g * av.z + xv.z) * sc + sh;
    o.w = (g * av.w + xv.w) * sc + sh;
    ((float4*)out)[i4] = o;
}

// ---------------- launch ----------------
extern "C" void kernel_launch(void* const* d_in, const int* in_sizes, int n_in,
                              void* d_out, int out_size)
{
    const float* x     = (const float*)d_in[0];
    const float* Wq    = (const float*)d_in[1];
    const float* bq    = (const float*)d_in[2];
    const float* Wk    = (const float*)d_in[3];
    const float* bk    = (const float*)d_in[4];
    const float* Wv    = (const float*)d_in[5];
    const float* bv    = (const float*)d_in[6];
    const float* gamma = (const float*)d_in[7];
    const float* bn_w  = (const float*)d_in[8];
    const float* bn_b  = (const float*)d_in[9];
    float* out = (float*)d_out;

    float *qkv, *energy, *ao, *mean, *var;
    cudaGetSymbolAddress((void**)&qkv,    g_qkv);
    cudaGetSymbolAddress((void**)&energy, g_energy);
    cudaGetSymbolAddress((void**)&ao,     g_ao);
    cudaGetSymbolAddress((void**)&mean,   g_mean);
    cudaGetSymbolAddress((void**)&var,    g_var);

    const size_t xbs   = (size_t)CH * NPIX;
    const size_t qkvbs = (size_t)QKV_ROWS * NPIX;
    const size_t ebs   = (size_t)NPIX * NPIX;
    dim3 blk(256);

    // q = Wq @ x : A k-contig, B n-contig, bias. M=64, K=512
    gemm_tf32_pipe<0, 0, true><<<dim3(NPIX / BN, 1, BATCH), blk>>>(
        Wq, 0, CH, x, xbs, NPIX, qkv, qkvbs, NPIX, bq, CQK, CH);
    // k = Wk @ x
    gemm_tf32_pipe<0, 0, true><<<dim3(NPIX / BN, 1, BATCH), blk>>>(
        Wk, 0, CH, x, xbs, NPIX, qkv + (size_t)CQK * NPIX, qkvbs, NPIX, bk, CQK, CH);
    // v = Wv @ x : M=512, K=512
    gemm_tf32_pipe<0, 0, true><<<dim3(NPIX / BN, CH / BM, BATCH), blk>>>(
        Wv, 0, CH, x, xbs, NPIX, qkv + (size_t)2 * CQK * NPIX, qkvbs, NPIX, bv, CH, CH);

    // energy(i,j) = sum_k q(k,i)*k(k,j) : A m-contig, B n-contig. M=N=4096, K=64
    gemm_tf32_pipe<1, 0, false><<<dim3(NPIX / BN, NPIX / BM, BATCH), blk>>>(
        qkv, qkvbs, NPIX,
        qkv + (size_t)CQK * NPIX, qkvbs, NPIX,
        energy, ebs, NPIX, nullptr, NPIX, CQK);

    // softmax over rows
    softmax_rows<<<BATCH * NPIX, 256>>>(energy);

    // ao(c,i) = sum_j v(c,j)*attn(i,j) : A k-contig, B k-contig. M=512, K=4096
    gemm_tf32_pipe<0, 1, false><<<dim3(NPIX / BN, CH / BM, BATCH), blk>>>(
        qkv + (size_t)2 * CQK * NPIX, qkvbs, NPIX,
        energy, ebs, NPIX,
        ao, (size_t)CH * NPIX, NPIX, nullptr, CH, NPIX);

    // stats, then fused residual+BN apply
    residual_stats<<<CH, 256>>>(ao, x, gamma, mean, var);
    bn_apply<<<(unsigned)(((size_t)BATCH * CH * NPIX / 4) / 256), 256>>>(
        ao, x, gamma, out, mean, var, bn_w, bn_b);
}

// round 4
// speedup vs baseline: 7.9515x; 5.1816x over previous
#include <cuda_runtime.h>
#include <cuda_fp16.h>
#include <mma.h>
#include <cstdint>

using namespace nvcuda;

#define BATCH 4
#define CH    512
#define CQK   64
#define NPIX  4096
#define EPS   1e-5f

#define BM 128
#define BN 128
#define BK 32
#define LDA0 40    // As[m][k] rows of BK+8 half  (AMODE 0: k-contig gmem)
#define LDA1 136   // As[k][m] rows of BM+8 half  (AMODE 1: m-contig gmem)
#define LDB0 136   // Bs[k][n] rows of BN+8 half  (BMODE 0: n-contig gmem)
#define LDB1 40    // Bs[n][k] rows of BK+8 half  (BMODE 1: k-contig gmem)

// ---------------- scratch (device globals; allocation-free) ----------------
__device__ __half g_xh[(size_t)BATCH * CH * NPIX];
__device__ __half g_wqh[CQK * CH];
__device__ __half g_wkh[CQK * CH];
__device__ __half g_wvh[CH * CH];
__device__ __half g_qh[(size_t)BATCH * CQK * NPIX];
__device__ __half g_kh[(size_t)BATCH * CQK * NPIX];
__device__ __half g_vh[(size_t)BATCH * CH * NPIX];
__device__ float  g_energy[(size_t)BATCH * NPIX * NPIX];
__device__ __half g_attnh[(size_t)BATCH * NPIX * NPIX];
__device__ float  g_ao[(size_t)BATCH * CH * NPIX];
__device__ float  g_mean[CH];
__device__ float  g_var[CH];

// ---------------- cp.async helpers ----------------
__device__ __forceinline__ void cp16(__half* dst, const __half* src) {
    unsigned d = (unsigned)__cvta_generic_to_shared(dst);
    asm volatile("cp.async.cg.shared.global [%0], [%1], 16;\n" :: "r"(d), "l"(src));
}
__device__ __forceinline__ void cp_commit() {
    asm volatile("cp.async.commit_group;\n" ::: "memory");
}
__device__ __forceinline__ void cp_wait1() {
    asm volatile("cp.async.wait_group 1;\n" ::: "memory");
}
__device__ __forceinline__ void cp_wait0() {
    asm volatile("cp.async.wait_group 0;\n" ::: "memory");
}

// ---------------- fp16 WMMA GEMM, true 2-stage pipeline ----------------
// D[b](m,n) = sum_k A(m,k) * B(k,n) (+ bias[m])
// AMODE 0: A(m,k) at A[m*lda + k]  (k contig) | AMODE 1: A(m,k) at A[k*lda + m] (m contig)
// BMODE 0: B(k,n) at B[k*ldb + n]  (n contig) | BMODE 1: B(k,n) at B[n*ldb + k] (k contig)
// DUAL: A rows 0..63 from A0, 64..127 from A1 (weights; Abatch ignored). M must cover tiles.
// OUTH: D is half (D0/D1 split at row 64 when DUAL), else fp32 D0.
template<int AMODE, int BMODE, bool DUAL, bool BIAS, bool OUTH>
__global__ __launch_bounds__(256, 2) void hgemm(
    const __half* __restrict__ A0, const __half* __restrict__ A1,
    size_t Abatch, int lda,
    const __half* __restrict__ B, size_t Bbatch, int ldb,
    void* __restrict__ D0, void* __restrict__ D1, size_t Dbatch, int ldd,
    const float* __restrict__ bias0, const float* __restrict__ bias1, int K)
{
    constexpr int ASZ = (AMODE == 0) ? BM * LDA0 : BK * LDA1;
    constexpr int BSZ = (BMODE == 0) ? BK * LDB0 : BN * LDB1;
    __shared__ __half sm[2][ASZ + BSZ];

    const int bz = blockIdx.z;
    const __half* Ab = A0 + (size_t)bz * Abatch;
    const __half* Bb = B + (size_t)bz * Bbatch;

    const int m0 = blockIdx.y * BM;
    const int n0 = blockIdx.x * BN;
    const int tid = threadIdx.x;
    const int warp = tid >> 5;
    const int lane = tid & 31;
    const int wm = (warp >> 1) * 32;   // warp tile 32(m) x 64(n)
    const int wn = (warp & 1) * 64;

    wmma::fragment<wmma::accumulator, 16, 16, 16, float> acc[2][4];
#pragma unroll
    for (int i = 0; i < 2; i++)
#pragma unroll
        for (int j = 0; j < 4; j++)
            wmma::fill_fragment(acc[i][j], 0.0f);

    auto load_tile = [&](int s, int k0) {
        __half* As = sm[s];
        __half* Bs = sm[s] + ASZ;
        // A: 512 x 16B chunks (128x32 half)
#pragma unroll
        for (int r = 0; r < 2; r++) {
            int c = tid + r * 256;
            if (AMODE == 0) {
                int m = c >> 2, jc = c & 3;
                const __half* src;
                if (DUAL)
                    src = (m < 64 ? Ab + (size_t)m * lda
                                  : A1 + (size_t)(m - 64) * lda) + k0 + jc * 8;
                else
                    src = Ab + (size_t)(m0 + m) * lda + k0 + jc * 8;
                cp16(&As[m * LDA0 + jc * 8], src);
            } else {
                int k = c >> 4, mc = c & 15;
                cp16(&As[k * LDA1 + mc * 8],
                     Ab + (size_t)(k0 + k) * lda + m0 + mc * 8);
            }
        }
        // B: 512 x 16B chunks (32x128 half)
#pragma unroll
        for (int r = 0; r < 2; r++) {
            int c = tid + r * 256;
            if (BMODE == 0) {
                int k = c >> 4, nc = c & 15;
                cp16(&Bs[k * LDB0 + nc * 8],
                     Bb + (size_t)(k0 + k) * ldb + n0 + nc * 8);
            } else {
                int n = c >> 2, kc = c & 3;
                cp16(&Bs[n * LDB1 + kc * 8],
                     Bb + (size_t)(n0 + n) * ldb + k0 + kc * 8);
            }
        }
    };

    auto compute_tile = [&](int s) {
        const __half* As = sm[s];
        const __half* Bs = sm[s] + ASZ;
#pragma unroll
        for (int ks = 0; ks < BK; ks += 16) {
            wmma::fragment<wmma::matrix_a, 16, 16, 16, __half, wmma::row_major> ar[2];
            wmma::fragment<wmma::matrix_a, 16, 16, 16, __half, wmma::col_major> ac[2];
#pragma unroll
            for (int i = 0; i < 2; i++) {
                if (AMODE == 0)
                    wmma::load_matrix_sync(ar[i], &As[(wm + i * 16) * LDA0 + ks], LDA0);
                else
                    wmma::load_matrix_sync(ac[i], &As[ks * LDA1 + wm + i * 16], LDA1);
            }
#pragma unroll
            for (int j = 0; j < 4; j++) {
                wmma::fragment<wmma::matrix_b, 16, 16, 16, __half, wmma::row_major> br;
                wmma::fragment<wmma::matrix_b, 16, 16, 16, __half, wmma::col_major> bc;
                if (BMODE == 0)
                    wmma::load_matrix_sync(br, &Bs[ks * LDB0 + wn + j * 16], LDB0);
                else
                    wmma::load_matrix_sync(bc, &Bs[(wn + j * 16) * LDB1 + ks], LDB1);
#pragma unroll
                for (int i = 0; i < 2; i++) {
                    if (AMODE == 0 && BMODE == 0) wmma::mma_sync(acc[i][j], ar[i], br, acc[i][j]);
                    if (AMODE == 0 && BMODE == 1) wmma::mma_sync(acc[i][j], ar[i], bc, acc[i][j]);
                    if (AMODE == 1 && BMODE == 0) wmma::mma_sync(acc[i][j], ac[i], br, acc[i][j]);
                    if (AMODE == 1 && BMODE == 1) wmma::mma_sync(acc[i][j], ac[i], bc, acc[i][j]);
                }
            }
        }
    };

    const int KT = K / BK;
    load_tile(0, 0);
    cp_commit();
    for (int kt = 0; kt < KT; kt++) {
        // issue next load BEFORE waiting -> load(kt+1) overlaps compute(kt)
        if (kt + 1 < KT) {
            load_tile((kt + 1) & 1, (kt + 1) * BK);
            cp_commit();
            cp_wait1();          // stage kt complete, kt+1 still in flight
        } else {
            cp_wait0();
        }
        __syncthreads();
        compute_tile(kt & 1);
        __syncthreads();         // all warps done reading before buffer reuse
    }

    // ---- epilogue ----
    if (!OUTH) {
        float* Db = (float*)D0 + (size_t)bz * Dbatch;
#pragma unroll
        for (int i = 0; i < 2; i++) {
            int gm = m0 + wm + i * 16;
#pragma unroll
            for (int j = 0; j < 4; j++)
                wmma::store_matrix_sync(Db + (size_t)gm * ldd + n0 + wn + j * 16,
                                        acc[i][j], ldd, wmma::mem_row_major);
        }
    } else {
        float* stg = (float*)&sm[0][0] + warp * 256;
#pragma unroll
        for (int i = 0; i < 2; i++)
#pragma unroll
            for (int j = 0; j < 4; j++) {
                wmma::store_matrix_sync(stg, acc[i][j], 16, wmma::mem_row_major);
                __syncwarp();
#pragma unroll
                for (int e = 0; e < 8; e++) {
                    int el = lane + e * 32;
                    int r = el >> 4, cc = el & 15;
                    int gm = m0 + wm + i * 16 + r;
                    int gn = n0 + wn + j * 16 + cc;
                    float val = stg[el];
                    __half* outp;
                    int row;
                    if (DUAL) {
                        if (BIAS) val += (gm < 64) ? bias0[gm] : bias1[gm - 64];
                        outp = (__half*)(gm < 64 ? D0 : D1) + (size_t)bz * Dbatch;
                        row = gm & 63;
                    } else {
                        if (BIAS) val += bias0[gm];
                        outp = (__half*)D0 + (size_t)bz * Dbatch;
                        row = gm;
                    }
                    outp[(size_t)row * ldd + gn] = __float2half(val);
                }
                __syncwarp();
            }
    }
}

// ---------------- f32 -> f16 convert ----------------
__global__ __launch_bounds__(256) void f2h(const float* __restrict__ in,
                                           __half* __restrict__ out, int n4)
{
    int i = blockIdx.x * 256 + threadIdx.x;
    if (i < n4) {
        float4 v = ((const float4*)in)[i];
        __half2* o = (__half2*)out + 2 * (size_t)i;
        o[0] = __floats2half2_rn(v.x, v.y);
        o[1] = __floats2half2_rn(v.z, v.w);
    }
}

// ---------------- row softmax: fp32 energy in, fp16 attn out ----------------
__global__ __launch_bounds__(256) void softmax_rows(const float* __restrict__ E,
                                                    __half* __restrict__ A)
{
    __shared__ float row[NPIX];
    __shared__ float red[256];
    const float4* r4 = (const float4*)(E + (size_t)blockIdx.x * NPIX);
    __half2* a2 = (__half2*)(A + (size_t)blockIdx.x * NPIX);
    float4* row4 = (float4*)row;
    const int tid = threadIdx.x;

    float mx = -3.402823466e+38f;
#pragma unroll
    for (int i = 0; i < 4; i++) {
        int j = tid + i * 256;
        float4 v = r4[j];
        row4[j] = v;
        mx = fmaxf(mx, fmaxf(fmaxf(v.x, v.y), fmaxf(v.z, v.w)));
    }
    red[tid] = mx;
    __syncthreads();
    for (int s = 128; s > 0; s >>= 1) {
        if (tid < s) red[tid] = fmaxf(red[tid], red[tid + s]);
        __syncthreads();
    }
    const float m = red[0];
    __syncthreads();

    float sum = 0.0f;
#pragma unroll
    for (int i = 0; i < 4; i++) {
        int j = tid + i * 256;
        float4 v = row4[j];
        v.x = __expf(v.x - m); v.y = __expf(v.y - m);
        v.z = __expf(v.z - m); v.w = __expf(v.w - m);
        row4[j] = v;
        sum += v.x + v.y + v.z + v.w;
    }
    red[tid] = sum;
    __syncthreads();
    for (int s = 128; s > 0; s >>= 1) {
        if (tid < s) red[tid] += red[tid + s];
        __syncthreads();
    }
    const float inv = 1.0f / red[0];
    __syncthreads();

#pragma unroll
    for (int i = 0; i < 4; i++) {
        int j = tid + i * 256;
        float4 v = row4[j];
        a2[2 * j]     = __floats2half2_rn(v.x * inv, v.y * inv);
        a2[2 * j + 1] = __floats2half2_rn(v.z * inv, v.w * inv);
    }
}

// ---------------- per-channel batch stats ----------------
__global__ __launch_bounds__(256) void residual_stats(
    const float* __restrict__ ao, const float* __restrict__ x,
    const float* __restrict__ gamma,
    float* __restrict__ mean, float* __restrict__ var)
{
    __shared__ float r1[256], r2[256];
    const int c = blockIdx.x;
    const float g = gamma[0];
    float s1 = 0.0f, s2 = 0.0f;
#pragma unroll
    for (int b = 0; b < BATCH; b++) {
        const float4* a4 = (const float4*)(ao + ((size_t)b * CH + c) * NPIX);
        const float4* x4 = (const float4*)(x  + ((size_t)b * CH + c) * NPIX);
        for (int n = threadIdx.x; n < NPIX / 4; n += 256) {
            float4 av = a4[n], xv = x4[n];
            float v0 = g * av.x + xv.x, v1 = g * av.y + xv.y;
            float v2 = g * av.z + xv.z, v3 = g * av.w + xv.w;
            s1 += v0 + v1 + v2 + v3;
            s2 += v0 * v0 + v1 * v1 + v2 * v2 + v3 * v3;
        }
    }
    r1[threadIdx.x] = s1;
    r2[threadIdx.x] = s2;
    __syncthreads();
    for (int s = 128; s > 0; s >>= 1) {
        if (threadIdx.x < s) {
            r1[threadIdx.x] += r1[threadIdx.x + s];
            r2[threadIdx.x] += r2[threadIdx.x + s];
        }
        __syncthreads();
    }
    if (threadIdx.x == 0) {
        const float cnt = (float)(BATCH * NPIX);
        float m = r1[0] / cnt;
        mean[c] = m;
        var[c] = r2[0] / cnt - m * m;
    }
}

// ---------------- BN apply ----------------
__global__ __launch_bounds__(256) void bn_apply(
    const float* __restrict__ ao, const float* __restrict__ x,
    const float* __restrict__ gamma,
    float* __restrict__ out, const float* __restrict__ mean,
    const float* __restrict__ var, const float* __restrict__ w,
    const float* __restrict__ bb)
{
    size_t i4 = (size_t)blockIdx.x * 256 + threadIdx.x;
    const float g = gamma[0];
    int c = (int)((i4 >> 10) & (CH - 1));
    float sc = rsqrtf(var[c] + EPS) * w[c];
    float sh = bb[c] - mean[c] * sc;
    float4 av = ((const float4*)ao)[i4];
    float4 xv = ((const float4*)x)[i4];
    float4 o;
    o.x = (g * av.x + xv.x) * sc + sh;
    o.y = (g * av.y + xv.y) * sc + sh;
    o.z = (g * av.z + xv.z) * sc + sh;
    o.w = (g * av.w + xv.w) * sc + sh;
    ((float4*)out)[i4] = o;
}

// ---------------- launch ----------------
extern "C" void kernel_launch(void* const* d_in, const int* in_sizes, int n_in,
                              void* d_out, int out_size)
{
    const float* x     = (const float*)d_in[0];
    const float* Wq    = (const float*)d_in[1];
    const float* bq    = (const float*)d_in[2];
    const float* Wk    = (const float*)d_in[3];
    const float* bk    = (const float*)d_in[4];
    const float* Wv    = (const float*)d_in[5];
    const float* bv    = (const float*)d_in[6];
    const float* gamma = (const float*)d_in[7];
    const float* bn_w  = (const float*)d_in[8];
    const float* bn_b  = (const float*)d_in[9];
    float* out = (float*)d_out;

    __half *xh, *wqh, *wkh, *wvh, *qh, *kh, *vh, *attnh;
    float *energy, *ao, *mean, *var;
    cudaGetSymbolAddress((void**)&xh,     g_xh);
    cudaGetSymbolAddress((void**)&wqh,    g_wqh);
    cudaGetSymbolAddress((void**)&wkh,    g_wkh);
    cudaGetSymbolAddress((void**)&wvh,    g_wvh);
    cudaGetSymbolAddress((void**)&qh,     g_qh);
    cudaGetSymbolAddress((void**)&kh,     g_kh);
    cudaGetSymbolAddress((void**)&vh,     g_vh);
    cudaGetSymbolAddress((void**)&attnh,  g_attnh);
    cudaGetSymbolAddress((void**)&energy, g_energy);
    cudaGetSymbolAddress((void**)&ao,     g_ao);
    cudaGetSymbolAddress((void**)&mean,   g_mean);
    cudaGetSymbolAddress((void**)&var,    g_var);

    const size_t xbs = (size_t)CH * NPIX;     // x / xh / vh / ao batch stride
    const size_t qbs = (size_t)CQK * NPIX;    // qh / kh batch stride
    const size_t ebs = (size_t)NPIX * NPIX;   // energy / attn batch stride

    // 1) convert inputs to half
    f2h<<<(BATCH * CH * NPIX / 4 + 255) / 256, 256>>>(x, xh, BATCH * CH * NPIX / 4);
    f2h<<<(CQK * CH / 4 + 255) / 256, 256>>>(Wq, wqh, CQK * CH / 4);
    f2h<<<(CQK * CH / 4 + 255) / 256, 256>>>(Wk, wkh, CQK * CH / 4);
    f2h<<<(CH * CH / 4 + 255) / 256, 256>>>(Wv, wvh, CH * CH / 4);

    // 2) q,k = (Wq||Wk) @ x  -> half. M=128 (dual 64+64), K=512
    hgemm<0, 0, true, true, true><<<dim3(NPIX / BN, 1, BATCH), 256>>>(
        wqh, wkh, 0, CH, xh, xbs, NPIX, qh, kh, qbs, NPIX, bq, bk, CH);

    // 3) v = Wv @ x -> half. M=512, K=512
    hgemm<0, 0, false, true, true><<<dim3(NPIX / BN, CH / BM, BATCH), 256>>>(
        wvh, nullptr, 0, CH, xh, xbs, NPIX, vh, nullptr, xbs, NPIX, bv, nullptr, CH);

    // 4) energy(i,j) = sum_k q(k,i)*k(k,j) -> fp32. M=N=4096, K=64
    hgemm<1, 0, false, false, false><<<dim3(NPIX / BN, NPIX / BM, BATCH), 256>>>(
        qh, nullptr, qbs, NPIX, kh, qbs, NPIX, energy, nullptr, ebs, NPIX,
        nullptr, nullptr, CQK);

    // 5) softmax rows -> half attn
    softmax_rows<<<BATCH * NPIX, 256>>>(energy, attnh);

    // 6) ao(c,i) = sum_j v(c,j)*attn(i,j) -> fp32. M=512, K=4096
    hgemm<0, 1, false, false, false><<<dim3(NPIX / BN, CH / BM, BATCH), 256>>>(
        vh, nullptr, xbs, NPIX, attnh, ebs, NPIX, ao, nullptr, xbs, NPIX,
        nullptr, nullptr, NPIX);

    // 7) stats + fused residual/BN apply
    residual_stats<<<CH, 256>>>(ao, x, gamma, mean, var);
    bn_apply<<<(unsigned)(((size_t)BATCH * CH * NPIX / 4) / 256), 256>>>(
        ao, x, gamma, out, mean, var, bn_w, bn_b);
}